// round 14
// baseline (speedup 1.0000x reference)
#include <cuda_runtime.h>
#include <cuda_fp16.h>
#include <mma.h>
#include <cstdint>

using namespace nvcuda;

#define EPS 1e-5f

// ---- scratch (static device globals; no allocation at runtime) ----
static __device__ half g_x16[16 * 256 * 1024];  // X converted to half [b][c][p]
static __device__ half g_wq16[512 * 256];
static __device__ half g_wk16[512 * 256];
static __device__ half g_wv16[512 * 256];
static __device__ half g_w216[256 * 512];
static __device__ half g_q[16 * 512 * 1024];    // [b, h*64+d, i]
static __device__ half g_k[16 * 512 * 1024];    // [b, h*64+d, j]
static __device__ half g_v[16 * 512 * 1024];    // [b, h*64+d, j]
static __device__ half g_o[16 * 1024 * 512];    // [b, i, h*64+d], hardswish applied

__device__ __forceinline__ float hswish_f(float x) {
    return x * __saturatef((x + 3.0f) * (1.0f / 6.0f));
}

__device__ __forceinline__ uint32_t packh2(float a, float b) {
    __half2 h = __floats2half2_rn(a, b);
    return *reinterpret_cast<uint32_t*>(&h);
}

__device__ __forceinline__ uint32_t smem_u32(const void* p) {
    return (uint32_t)__cvta_generic_to_shared(p);
}
__device__ __forceinline__ void cp16(uint32_t dst, const void* src) {
    asm volatile("cp.async.cg.shared.global [%0], [%1], 16;" :: "r"(dst), "l"(src));
}
__device__ __forceinline__ void cp_commit() { asm volatile("cp.async.commit_group;"); }
template<int N> __device__ __forceinline__ void cp_wait() {
    asm volatile("cp.async.wait_group %0;" :: "n"(N));
}
__device__ __forceinline__ void ldsm_x4(uint32_t& r0, uint32_t& r1, uint32_t& r2, uint32_t& r3, uint32_t a) {
    asm volatile("ldmatrix.sync.aligned.m8n8.x4.shared.b16 {%0,%1,%2,%3}, [%4];"
        : "=r"(r0), "=r"(r1), "=r"(r2), "=r"(r3) : "r"(a));
}
__device__ __forceinline__ void ldsm_x4_t(uint32_t& r0, uint32_t& r1, uint32_t& r2, uint32_t& r3, uint32_t a) {
    asm volatile("ldmatrix.sync.aligned.m8n8.x4.trans.shared.b16 {%0,%1,%2,%3}, [%4];"
        : "=r"(r0), "=r"(r1), "=r"(r2), "=r"(r3) : "r"(a));
}

// mma.sync m16n8k16 row.col f32.f16.f16.f32, accumulate in place
__device__ __forceinline__ void mma16816(float* d, const uint32_t* a, uint32_t b0, uint32_t b1) {
    asm volatile(
        "mma.sync.aligned.m16n8k16.row.col.f32.f16.f16.f32 "
        "{%0,%1,%2,%3}, {%4,%5,%6,%7}, {%8,%9}, {%0,%1,%2,%3};\n"
        : "+f"(d[0]), "+f"(d[1]), "+f"(d[2]), "+f"(d[3])
        : "r"(a[0]), "r"(a[1]), "r"(a[2]), "r"(a[3]), "r"(b0), "r"(b1));
}

// ============================================================================
// Kernel 0: convert fp32 inputs to fp16 globals (4 floats per thread).
// ============================================================================
__global__ __launch_bounds__(256) void convert_kernel(
    const float* __restrict__ X, const float* __restrict__ Wq,
    const float* __restrict__ Wk, const float* __restrict__ Wv,
    const float* __restrict__ W2)
{
    int i = blockIdx.x * 256 + threadIdx.x;   // float4 index
    const int NX = 1048576, NW = 32768;       // in float4 units
    const float* src; half* dst; int off;
    if (i < NX)                 { src = X;  dst = g_x16;  off = i; }
    else if (i < NX + NW)       { src = Wq; dst = g_wq16; off = i - NX; }
    else if (i < NX + 2 * NW)   { src = Wk; dst = g_wk16; off = i - NX - NW; }
    else if (i < NX + 3 * NW)   { src = Wv; dst = g_wv16; off = i - NX - 2 * NW; }
    else if (i < NX + 4 * NW)   { src = W2; dst = g_w216; off = i - NX - 3 * NW; }
    else return;
    float4 f = ((const float4*)src)[off];
    half2* d2 = (half2*)(dst + (size_t)off * 4);
    d2[0] = __floats2half2_rn(f.x, f.y);
    d2[1] = __floats2half2_rn(f.z, f.w);
}

// ============================================================================
// Kernel 1: fused Q/K/V projection GEMM (fp16 wmma, cp.async 3-stage) + BN.
// out[b,o,p] = bn(sum_c W[o,c] * X[b,c,p]).  Tile 128o x 128p, 256 thr.
// smem: 3 stages x (Ws 128x40 half = 10240B | Xs 32x136 half = 8704B) = 56832.
// ============================================================================
__global__ __launch_bounds__(256, 2) void proj_kernel(
    const float* __restrict__ gq, const float* __restrict__ bq,
    const float* __restrict__ mq, const float* __restrict__ vq,
    const float* __restrict__ gk, const float* __restrict__ bk,
    const float* __restrict__ mk, const float* __restrict__ vk,
    const float* __restrict__ gv, const float* __restrict__ bv,
    const float* __restrict__ mv, const float* __restrict__ vv)
{
    extern __shared__ char ps[];
    __shared__ float so[128], to[128];
    __shared__ float Es[8][384];

    const int which = blockIdx.z >> 4;
    const int b     = blockIdx.z & 15;
    const half* W    = (which == 0) ? g_wq16 : (which == 1) ? g_wk16 : g_wv16;
    const float* gam = (which == 0) ? gq : (which == 1) ? gk : gv;
    const float* bet = (which == 0) ? bq : (which == 1) ? bk : bv;
    const float* mu  = (which == 0) ? mq : (which == 1) ? mk : mv;
    const float* var = (which == 0) ? vq : (which == 1) ? vk : vv;
    half* outbuf     = (which == 0) ? g_q : (which == 1) ? g_k : g_v;

    const int o0 = blockIdx.y * 128;
    const int p0 = blockIdx.x * 128;
    const int tid  = threadIdx.x;
    const int warp = tid >> 5;
    const int lane = tid & 31;
    const half* Xb = g_x16 + (size_t)b * 256 * 1024;

    if (tid < 128) {
        int o = o0 + tid;
        float s = gam[o] * rsqrtf(var[o] + EPS);
        so[tid] = s;
        to[tid] = bet[o] - mu[o] * s;
    }

    const uint32_t sm0 = smem_u32(ps);
    auto issue = [&](int t, int s) {
        int kk = t * 32;
        uint32_t base = sm0 + s * 18944;
#pragma unroll
        for (int u = 0; u < 2; u++) {
            int c = tid + u * 256;                  // 0..511
            int o = c >> 2, ko = (c & 3) * 8;
            cp16(base + (o * 40 + ko) * 2, W + (size_t)(o0 + o) * 256 + kk + ko);
            int kc = c >> 4, po = (c & 15) * 8;
            cp16(base + 10240 + (kc * 136 + po) * 2, Xb + (size_t)(kk + kc) * 1024 + p0 + po);
        }
    };

    const int wo = (warp >> 1) * 32;
    const int wp = (warp & 1) * 64;

    wmma::fragment<wmma::accumulator, 16, 16, 16, float> acc[2][4];
#pragma unroll
    for (int i = 0; i < 2; i++)
#pragma unroll
        for (int j = 0; j < 4; j++) wmma::fill_fragment(acc[i][j], 0.0f);

    issue(0, 0); cp_commit();
    issue(1, 1); cp_commit();

    for (int t = 0; t < 8; t++) {
        if (t < 7) cp_wait<1>(); else cp_wait<0>();
        __syncthreads();
        if (t + 2 < 8) { issue(t + 2, (t + 2) % 3); cp_commit(); }
        const half* Wst = (const half*)(ps + (t % 3) * 18944);
        const half* Xst = (const half*)(ps + (t % 3) * 18944 + 10240);
#pragma unroll
        for (int ks = 0; ks < 32; ks += 16) {
            wmma::fragment<wmma::matrix_a, 16, 16, 16, half, wmma::row_major> a[2];
            wmma::load_matrix_sync(a[0], Wst + wo * 40 + ks, 40);
            wmma::load_matrix_sync(a[1], Wst + (wo + 16) * 40 + ks, 40);
#pragma unroll
            for (int nf = 0; nf < 4; nf++) {
                wmma::fragment<wmma::matrix_b, 16, 16, 16, half, wmma::row_major> bf;
                wmma::load_matrix_sync(bf, Xst + ks * 136 + wp + nf * 16, 136);
                wmma::mma_sync(acc[0][nf], a[0], bf, acc[0][nf]);
                wmma::mma_sync(acc[1][nf], a[1], bf, acc[1][nf]);
            }
        }
    }
    __syncthreads();

    // Epilogue: BN, convert half, store [o][p]
    float* es = &Es[warp][0];
#pragma unroll
    for (int mf = 0; mf < 2; mf++)
#pragma unroll
        for (int nf = 0; nf < 4; nf++) {
            wmma::store_matrix_sync(es, acc[mf][nf], 24, wmma::mem_row_major);
            __syncwarp();
            int r = lane >> 1, cb = (lane & 1) * 8;
            int o_l = wo + mf * 16 + r;
            float s = so[o_l], t = to[o_l];
            union { uint4 u; half h[8]; } hb;
#pragma unroll
            for (int c = 0; c < 8; c++)
                hb.h[c] = __float2half(es[r * 24 + cb + c] * s + t);
            int o = o0 + o_l;
            int p = p0 + wp + nf * 16 + cb;
            *(uint4*)(outbuf + ((size_t)(b * 512 + o) * 1024 + p)) = hb.u;
            __syncwarp();
        }
}

// ============================================================================
// Kernel 2: attention, mma.sync + ldmatrix, cp.async 3-stage K/V, in-register
// streaming softmax (no max-sub, |S|<~6), hardswish fused into epilogue.
// smem: Qs 64x136 (17408) | Ks 3x64x72 (27648) | Vs 3x64x72 (27648) |
//       semb 4096  => 76800 B
// ============================================================================
__global__ __launch_bounds__(256, 2) void attn_kernel(const float* __restrict__ emb)
{
    extern __shared__ char smc[];
    half*  Qs   = (half*)(smc);
    half*  Ks   = (half*)(smc + 17408);
    half*  Vs   = (half*)(smc + 45056);
    float* semb = (float*)(smc + 72704);

    const int bh = blockIdx.y;
    const int b = bh >> 3, h = bh & 7;
    const int i0 = blockIdx.x * 128;
    const int tid  = threadIdx.x;
    const int warp = tid >> 5;
    const int lane = tid & 31;
    const int g    = lane >> 2;
    const int tig  = lane & 3;

    const half* Qg = g_q + (size_t)(b * 512 + h * 64) * 1024;
    const half* Kg = g_k + (size_t)(b * 512 + h * 64) * 1024;
    const half* Vg = g_v + (size_t)(b * 512 + h * 64) * 1024;

    const uint32_t qsm = smem_u32(Qs);
    const uint32_t ksm = smem_u32(Ks);
    const uint32_t vsm = smem_u32(Vs);

    for (int i = tid; i < 1024; i += 256)
        semb[i] = emb[i * 8 + h] * 8.0f;

    // Q: 64 d-rows x 128 i, stride 136 (natural [d][i], no transpose)
#pragma unroll
    for (int u = 0; u < 4; u++) {
        int c = tid + u * 256;
        int d = c >> 4, io = (c & 15) * 8;
        cp16(qsm + (d * 136 + io) * 2, Qg + (size_t)d * 1024 + i0 + io);
    }

    auto issue_kv = [&](int t, int s) {
        int j0 = t * 64;
        uint32_t kb = ksm + s * 9216, vb = vsm + s * 9216;
#pragma unroll
        for (int u = 0; u < 2; u++) {
            int c = tid + u * 256;
            int d = c >> 3, jo = (c & 7) * 8;
            cp16(kb + (d * 72 + jo) * 2, Kg + (size_t)d * 1024 + j0 + jo);
            cp16(vb + (d * 72 + jo) * 2, Vg + (size_t)d * 1024 + j0 + jo);
        }
    };

    issue_kv(0, 0); cp_commit();   // G0 (with Q)
    issue_kv(1, 1); cp_commit();   // G1
    cp_wait<1>();                  // G0 done
    __syncthreads();

    // Q A-fragments via ldmatrix.trans from [d][i]
    const int iw = warp * 16;
    const int l = lane;
    const int qRow = (l & 7) + (l >> 4) * 8;            // d-row within 16
    const int qCol = iw + ((l >> 3) & 1) * 8;           // i (+8 for a1/a3)
    uint32_t qa[4][4];
#pragma unroll
    for (int dk = 0; dk < 4; dk++)
        ldsm_x4_t(qa[dk][0], qa[dk][1], qa[dk][2], qa[dk][3],
                  qsm + ((dk * 16 + qRow) * 136 + qCol) * 2);

    const int kRow  = (l & 7) + ((l >> 3) & 1) * 8;     // d within 16 (b0/b1)
    const int kCol8 = (l >> 4) * 8;                     // j +8 for second nf
    const int vRow  = (l & 7) + (l >> 4) * 8;           // d (n-dim)
    const int vCol8 = ((l >> 3) & 1) * 8;               // j +8 for b1

    const int ig  = i0 + iw + g;
    const int ig8 = ig + 8;
    const int xi0 = ig >> 5,  yi0 = ig & 31;
    const int xi8 = ig8 >> 5, yi8 = ig8 & 31;

    float oacc[8][4];
#pragma unroll
    for (int nf = 0; nf < 8; nf++)
#pragma unroll
        for (int c = 0; c < 4; c++) oacc[nf][c] = 0.0f;
    float l0 = 0.0f, l1 = 0.0f;

    for (int t = 0; t < 16; t++) {
        if (t < 15) cp_wait<1>(); else cp_wait<0>();
        __syncthreads();
        if (t + 2 < 16) { issue_kv(t + 2, (t + 2) % 3); cp_commit(); }

        const uint32_t kb = ksm + (t % 3) * 9216;
        const uint32_t vb = vsm + (t % 3) * 9216;

        // S = Q K^T (K via ldmatrix.trans from natural [d][j])
        float sacc[8][4];
#pragma unroll
        for (int nf = 0; nf < 8; nf++)
#pragma unroll
            for (int c = 0; c < 4; c++) sacc[nf][c] = 0.0f;
#pragma unroll
        for (int dk = 0; dk < 4; dk++) {
#pragma unroll
            for (int nfp = 0; nfp < 4; nfp++) {
                uint32_t b0a, b1a, b0b, b1b;
                ldsm_x4_t(b0a, b1a, b0b, b1b,
                          kb + ((dk * 16 + kRow) * 72 + nfp * 16 + kCol8) * 2);
                mma16816(sacc[2 * nfp],     qa[dk], b0a, b1a);
                mma16816(sacc[2 * nfp + 1], qa[dk], b0b, b1b);
            }
        }

        // bias + exp, in registers
        const int jt = t * 64 + 2 * tig;
#pragma unroll
        for (int nf = 0; nf < 8; nf++) {
            int j0e = jt + nf * 8;
            int xj0 = j0e >> 5,       yj0 = j0e & 31;
            int xj1 = (j0e + 1) >> 5, yj1 = (j0e + 1) & 31;
            float bi00 = semb[abs(xi0 - xj0) * 32 + abs(yi0 - yj0)];
            float bi01 = semb[abs(xi0 - xj1) * 32 + abs(yi0 - yj1)];
            float bi10 = semb[abs(xi8 - xj0) * 32 + abs(yi8 - yj0)];
            float bi11 = semb[abs(xi8 - xj1) * 32 + abs(yi8 - yj1)];
            float e0 = __expf(fmaf(sacc[nf][0], 0.125f, bi00));
            float e1 = __expf(fmaf(sacc[nf][1], 0.125f, bi01));
            float e2 = __expf(fmaf(sacc[nf][2], 0.125f, bi10));
            float e3 = __expf(fmaf(sacc[nf][3], 0.125f, bi11));
            l0 += e0 + e1;
            l1 += e2 + e3;
            sacc[nf][0] = e0; sacc[nf][1] = e1;
            sacc[nf][2] = e2; sacc[nf][3] = e3;
        }

        // O += P V (V non-trans ldmatrix from natural [d][j])
#pragma unroll
        for (int kf = 0; kf < 4; kf++) {
            uint32_t pa[4];
            pa[0] = packh2(sacc[2 * kf][0],     sacc[2 * kf][1]);
            pa[1] = packh2(sacc[2 * kf][2],     sacc[2 * kf][3]);
            pa[2] = packh2(sacc[2 * kf + 1][0], sacc[2 * kf + 1][1]);
            pa[3] = packh2(sacc[2 * kf + 1][2], sacc[2 * kf + 1][3]);
#pragma unroll
            for (int nfp = 0; nfp < 4; nfp++) {
                uint32_t v0a, v1a, v0b, v1b;
                ldsm_x4(v0a, v1a, v0b, v1b,
                        vb + ((nfp * 16 + vRow) * 72 + kf * 16 + vCol8) * 2);
                mma16816(oacc[2 * nfp],     pa, v0a, v1a);
                mma16816(oacc[2 * nfp + 1], pa, v0b, v1b);
            }
        }
    }

    // row-sum reduction within quad, normalize, hardswish, store
    l0 += __shfl_xor_sync(0xffffffffu, l0, 1);
    l0 += __shfl_xor_sync(0xffffffffu, l0, 2);
    l1 += __shfl_xor_sync(0xffffffffu, l1, 1);
    l1 += __shfl_xor_sync(0xffffffffu, l1, 2);
    float inv0 = 1.0f / l0, inv1 = 1.0f / l1;

    half* dst0 = g_o + ((size_t)(b * 1024 + ig)  * 512 + h * 64);
    half* dst1 = g_o + ((size_t)(b * 1024 + ig8) * 512 + h * 64);
#pragma unroll
    for (int nf = 0; nf < 8; nf++) {
        *(__half2*)(dst0 + nf * 8 + 2 * tig) =
            __floats2half2_rn(hswish_f(oacc[nf][0] * inv0), hswish_f(oacc[nf][1] * inv0));
        *(__half2*)(dst1 + nf * 8 + 2 * tig) =
            __floats2half2_rn(hswish_f(oacc[nf][2] * inv1), hswish_f(oacc[nf][3] * inv1));
    }
}

// ============================================================================
// Kernel 3: output GEMM (pure fp16, cp.async 3-stage) + bias + BN.
// g_o already holds hardswish(attn_out).  A=[p][c], B=W2h[o][c] col -> (p,o).
// smem: 3 stages x (As 10240 + Bs 10240) = 61440 B.
// ============================================================================
__global__ __launch_bounds__(256, 2) void outproj_kernel(
    const float* __restrict__ b_out,
    const float* __restrict__ gam, const float* __restrict__ bet,
    const float* __restrict__ mu, const float* __restrict__ var,
    float* __restrict__ out)
{
    extern __shared__ char ps[];
    __shared__ float so[128], to[128], bo_s[128];
    __shared__ float Es[8][384];

    const int b  = blockIdx.z;
    const int o0 = blockIdx.y * 128;
    const int p0 = blockIdx.x * 128;
    const int tid  = threadIdx.x;
    const int warp = tid >> 5;
    const int lane = tid & 31;
    const half* Ob = g_o + (size_t)b * 1024 * 512;

    if (tid < 128) {
        int o = o0 + tid;
        float s = gam[o] * rsqrtf(var[o] + EPS);
        so[tid] = s;
        to[tid] = bet[o] - mu[o] * s;
        bo_s[tid] = b_out[o];
    }

    const uint32_t sm0 = smem_u32(ps);
    auto issue = [&](int t, int s) {
        int kk = t * 32;
        uint32_t base = sm0 + s * 20480;
#pragma unroll
        for (int u = 0; u < 2; u++) {
            int c = tid + u * 256;
            int r = c >> 2, ko = (c & 3) * 8;
            cp16(base + (r * 40 + ko) * 2, Ob + (size_t)(p0 + r) * 512 + kk + ko);
            cp16(base + 10240 + (r * 40 + ko) * 2, g_w216 + (size_t)(o0 + r) * 512 + kk + ko);
        }
    };

    const int wp = (warp >> 1) * 32;
    const int wo = (warp & 1) * 64;

    wmma::fragment<wmma::accumulator, 16, 16, 16, float> acc[2][4];
#pragma unroll
    for (int i = 0; i < 2; i++)
#pragma unroll
        for (int j = 0; j < 4; j++) wmma::fill_fragment(acc[i][j], 0.0f);

    issue(0, 0); cp_commit();
    issue(1, 1); cp_commit();

    for (int t = 0; t < 16; t++) {
        if (t < 15) cp_wait<1>(); else cp_wait<0>();
        __syncthreads();
        if (t + 2 < 16) { issue(t + 2, (t + 2) % 3); cp_commit(); }
        const half* As = (const half*)(ps + (t % 3) * 20480);
        const half* Bs = (const half*)(ps + (t % 3) * 20480 + 10240);
#pragma unroll
        for (int ks = 0; ks < 32; ks += 16) {
            wmma::fragment<wmma::matrix_a, 16, 16, 16, half, wmma::row_major> a[2];
            wmma::load_matrix_sync(a[0], As + wp * 40 + ks, 40);
            wmma::load_matrix_sync(a[1], As + (wp + 16) * 40 + ks, 40);
#pragma unroll
            for (int nf = 0; nf < 4; nf++) {
                wmma::fragment<wmma::matrix_b, 16, 16, 16, half, wmma::col_major> bf;
                wmma::load_matrix_sync(bf, Bs + (wo + nf * 16) * 40 + ks, 40);
                wmma::mma_sync(acc[0][nf], a[0], bf, acc[0][nf]);
                wmma::mma_sync(acc[1][nf], a[1], bf, acc[1][nf]);
            }
        }
    }
    __syncthreads();

    // Epilogue: acc (m=p, n=o); col-major store -> es[o][p], BN per o, fp32 out
    float* es = &Es[warp][0];
#pragma unroll
    for (int mf = 0; mf < 2; mf++)
#pragma unroll
        for (int nf = 0; nf < 4; nf++) {
            wmma::store_matrix_sync(es, acc[mf][nf], 24, wmma::mem_col_major);
            __syncwarp();
            int r = lane >> 1, cb = (lane & 1) * 8;
            int o_l = wo + nf * 16 + r;
            int p_l = wp + mf * 16 + cb;
            float s = so[o_l], t = to[o_l], bb = bo_s[o_l];
            float* dst = out + (size_t)(b * 256 + o0 + o_l) * 1024 + p0 + p_l;
            const float* er = es + r * 24 + cb;
            float4 v0, v1;
            v0.x = (er[0] + bb) * s + t;  v0.y = (er[1] + bb) * s + t;
            v0.z = (er[2] + bb) * s + t;  v0.w = (er[3] + bb) * s + t;
            v1.x = (er[4] + bb) * s + t;  v1.y = (er[5] + bb) * s + t;
            v1.z = (er[6] + bb) * s + t;  v1.w = (er[7] + bb) * s + t;
            *(float4*)dst = v0;
            *(float4*)(dst + 4) = v1;
            __syncwarp();
        }
}

// ============================================================================
extern "C" void kernel_launch(void* const* d_in, const int* in_sizes, int n_in,
                              void* d_out, int out_size)
{
    const float* x    = (const float*)d_in[0];
    const float* wq   = (const float*)d_in[1];
    const float* gq   = (const float*)d_in[2];
    const float* bq   = (const float*)d_in[3];
    const float* mq   = (const float*)d_in[4];
    const float* vq   = (const float*)d_in[5];
    const float* wk   = (const float*)d_in[6];
    const float* gk   = (const float*)d_in[7];
    const float* bk   = (const float*)d_in[8];
    const float* mk   = (const float*)d_in[9];
    const float* vk   = (const float*)d_in[10];
    const float* wv   = (const float*)d_in[11];
    const float* gv   = (const float*)d_in[12];
    const float* bv   = (const float*)d_in[13];
    const float* mv   = (const float*)d_in[14];
    const float* vv   = (const float*)d_in[15];
    const float* emb  = (const float*)d_in[16];
    const float* w_o  = (const float*)d_in[17];
    const float* b_o  = (const float*)d_in[18];
    const float* go   = (const float*)d_in[19];
    const float* bo   = (const float*)d_in[20];
    const float* mo   = (const float*)d_in[21];
    const float* vo   = (const float*)d_in[22];
    // d_in[23] = pos_indices: recomputed on the fly in attn_kernel, unused.

    cudaFuncSetAttribute(proj_kernel,    cudaFuncAttributeMaxDynamicSharedMemorySize, 56832);
    cudaFuncSetAttribute(attn_kernel,    cudaFuncAttributeMaxDynamicSharedMemorySize, 76800);
    cudaFuncSetAttribute(outproj_kernel, cudaFuncAttributeMaxDynamicSharedMemorySize, 61440);
    cudaFuncSetAttribute(proj_kernel,    cudaFuncAttributePreferredSharedMemoryCarveout, 100);
    cudaFuncSetAttribute(attn_kernel,    cudaFuncAttributePreferredSharedMemoryCarveout, 100);
    cudaFuncSetAttribute(outproj_kernel, cudaFuncAttributePreferredSharedMemoryCarveout, 100);

    convert_kernel<<<4608, 256>>>(x, wq, wk, wv, w_o);
    proj_kernel<<<dim3(8, 4, 48), 256, 56832>>>(gq, bq, mq, vq,
                                                gk, bk, mk, vk,
                                                gv, bv, mv, vv);
    attn_kernel<<<dim3(8, 128), 256, 76800>>>(emb);
    outproj_kernel<<<dim3(8, 2, 16), 256, 61440>>>(b_o, go, bo, mo, vo, (float*)d_out);
}

// round 16
// speedup vs baseline: 1.0030x; 1.0030x over previous
#include <cuda_runtime.h>
#include <cuda_fp16.h>
#include <mma.h>
#include <cstdint>

using namespace nvcuda;

#define EPS 1e-5f

// ---- scratch (static device globals; no allocation at runtime) ----
static __device__ half g_x16[16 * 256 * 1024];  // X converted to half [b][c][p]
static __device__ half g_wq16[512 * 256];
static __device__ half g_wk16[512 * 256];
static __device__ half g_wv16[512 * 256];
static __device__ half g_w216[256 * 512];
static __device__ half g_q[16 * 512 * 1024];    // [b, h*64+d, i], pre-scaled by 0.125
static __device__ half g_k[16 * 512 * 1024];    // [b, h*64+d, j]
static __device__ half g_v[16 * 512 * 1024];    // [b, h*64+d, j]
static __device__ half g_o[16 * 1024 * 512];    // [b, i, h*64+d], hardswish applied

__device__ __forceinline__ float hswish_f(float x) {
    return x * __saturatef((x + 3.0f) * (1.0f / 6.0f));
}

__device__ __forceinline__ uint32_t packh2(float a, float b) {
    __half2 h = __floats2half2_rn(a, b);
    return *reinterpret_cast<uint32_t*>(&h);
}

__device__ __forceinline__ uint32_t smem_u32(const void* p) {
    return (uint32_t)__cvta_generic_to_shared(p);
}
__device__ __forceinline__ void cp16(uint32_t dst, const void* src) {
    asm volatile("cp.async.cg.shared.global [%0], [%1], 16;" :: "r"(dst), "l"(src));
}
__device__ __forceinline__ void cp_commit() { asm volatile("cp.async.commit_group;"); }
template<int N> __device__ __forceinline__ void cp_wait() {
    asm volatile("cp.async.wait_group %0;" :: "n"(N));
}
__device__ __forceinline__ void ldsm_x4(uint32_t& r0, uint32_t& r1, uint32_t& r2, uint32_t& r3, uint32_t a) {
    asm volatile("ldmatrix.sync.aligned.m8n8.x4.shared.b16 {%0,%1,%2,%3}, [%4];"
        : "=r"(r0), "=r"(r1), "=r"(r2), "=r"(r3) : "r"(a));
}
__device__ __forceinline__ void ldsm_x4_t(uint32_t& r0, uint32_t& r1, uint32_t& r2, uint32_t& r3, uint32_t a) {
    asm volatile("ldmatrix.sync.aligned.m8n8.x4.trans.shared.b16 {%0,%1,%2,%3}, [%4];"
        : "=r"(r0), "=r"(r1), "=r"(r2), "=r"(r3) : "r"(a));
}

// mma.sync m16n8k16 row.col f32 accumulate, in place
__device__ __forceinline__ void mma16816(float* d, const uint32_t* a, uint32_t b0, uint32_t b1) {
    asm volatile(
        "mma.sync.aligned.m16n8k16.row.col.f32.f16.f16.f32 "
        "{%0,%1,%2,%3}, {%4,%5,%6,%7}, {%8,%9}, {%0,%1,%2,%3};\n"
        : "+f"(d[0]), "+f"(d[1]), "+f"(d[2]), "+f"(d[3])
        : "r"(a[0]), "r"(a[1]), "r"(a[2]), "r"(a[3]), "r"(b0), "r"(b1));
}

// mma.sync m16n8k16 row.col fp16 accumulate (2 packed half2 regs), in place
__device__ __forceinline__ void mma16816_h(uint32_t* d, const uint32_t* a, uint32_t b0, uint32_t b1) {
    asm volatile(
        "mma.sync.aligned.m16n8k16.row.col.f16.f16.f16.f16 "
        "{%0,%1}, {%2,%3,%4,%5}, {%6,%7}, {%0,%1};\n"
        : "+r"(d[0]), "+r"(d[1])
        : "r"(a[0]), "r"(a[1]), "r"(a[2]), "r"(a[3]), "r"(b0), "r"(b1));
}

// ============================================================================
// Kernel 0: convert fp32 inputs to fp16 globals (4 floats per thread).
// ============================================================================
__global__ __launch_bounds__(256) void convert_kernel(
    const float* __restrict__ X, const float* __restrict__ Wq,
    const float* __restrict__ Wk, const float* __restrict__ Wv,
    const float* __restrict__ W2)
{
    int i = blockIdx.x * 256 + threadIdx.x;   // float4 index
    const int NX = 1048576, NW = 32768;       // in float4 units
    const float* src; half* dst; int off;
    if (i < NX)                 { src = X;  dst = g_x16;  off = i; }
    else if (i < NX + NW)       { src = Wq; dst = g_wq16; off = i - NX; }
    else if (i < NX + 2 * NW)   { src = Wk; dst = g_wk16; off = i - NX - NW; }
    else if (i < NX + 3 * NW)   { src = Wv; dst = g_wv16; off = i - NX - 2 * NW; }
    else if (i < NX + 4 * NW)   { src = W2; dst = g_w216; off = i - NX - 3 * NW; }
    else return;
    float4 f = ((const float4*)src)[off];
    half2* d2 = (half2*)(dst + (size_t)off * 4);
    d2[0] = __floats2half2_rn(f.x, f.y);
    d2[1] = __floats2half2_rn(f.z, f.w);
}

// ============================================================================
// Kernel 1: fused Q/K/V projection GEMM (fp16 wmma, cp.async 4-stage) + BN.
// Q is additionally pre-scaled by 0.125 (attention scale folded in).
// smem: 4 stages x (Ws 128x40 = 10240B | Xs 32x136 = 8704B) = 75776 B.
// ============================================================================
__global__ __launch_bounds__(256, 2) void proj_kernel(
    const float* __restrict__ gq, const float* __restrict__ bq,
    const float* __restrict__ mq, const float* __restrict__ vq,
    const float* __restrict__ gk, const float* __restrict__ bk,
    const float* __restrict__ mk, const float* __restrict__ vk,
    const float* __restrict__ gv, const float* __restrict__ bv,
    const float* __restrict__ mv, const float* __restrict__ vv)
{
    extern __shared__ char ps[];
    __shared__ float so[128], to[128];
    __shared__ float Es[8][384];

    const int which = blockIdx.z >> 4;
    const int b     = blockIdx.z & 15;
    const half* W    = (which == 0) ? g_wq16 : (which == 1) ? g_wk16 : g_wv16;
    const float* gam = (which == 0) ? gq : (which == 1) ? gk : gv;
    const float* bet = (which == 0) ? bq : (which == 1) ? bk : bv;
    const float* mu  = (which == 0) ? mq : (which == 1) ? mk : mv;
    const float* var = (which == 0) ? vq : (which == 1) ? vk : vv;
    half* outbuf     = (which == 0) ? g_q : (which == 1) ? g_k : g_v;
    const float qs   = (which == 0) ? 0.125f : 1.0f;

    const int o0 = blockIdx.y * 128;
    const int p0 = blockIdx.x * 128;
    const int tid  = threadIdx.x;
    const int warp = tid >> 5;
    const int lane = tid & 31;
    const half* Xb = g_x16 + (size_t)b * 256 * 1024;

    if (tid < 128) {
        int o = o0 + tid;
        float s = gam[o] * rsqrtf(var[o] + EPS) * qs;
        so[tid] = s;
        to[tid] = (bet[o] - mu[o] * gam[o] * rsqrtf(var[o] + EPS)) * qs;
    }

    const uint32_t sm0 = smem_u32(ps);
    auto issue = [&](int t, int s) {
        int kk = t * 32;
        uint32_t base = sm0 + s * 18944;
#pragma unroll
        for (int u = 0; u < 2; u++) {
            int c = tid + u * 256;                  // 0..511
            int o = c >> 2, ko = (c & 3) * 8;
            cp16(base + (o * 40 + ko) * 2, W + (size_t)(o0 + o) * 256 + kk + ko);
            int kc = c >> 4, po = (c & 15) * 8;
            cp16(base + 10240 + (kc * 136 + po) * 2, Xb + (size_t)(kk + kc) * 1024 + p0 + po);
        }
    };

    const int wo = (warp >> 1) * 32;
    const int wp = (warp & 1) * 64;

    wmma::fragment<wmma::accumulator, 16, 16, 16, float> acc[2][4];
#pragma unroll
    for (int i = 0; i < 2; i++)
#pragma unroll
        for (int j = 0; j < 4; j++) wmma::fill_fragment(acc[i][j], 0.0f);

    issue(0, 0); cp_commit();
    issue(1, 1); cp_commit();
    issue(2, 2); cp_commit();

    for (int t = 0; t < 8; t++) {
        if (t + 2 < 8)      cp_wait<2>();
        else if (t + 1 < 8) cp_wait<1>();
        else                cp_wait<0>();
        __syncthreads();
        if (t + 3 < 8) { issue(t + 3, (t + 3) & 3); cp_commit(); }
        const half* Wst = (const half*)(ps + (t & 3) * 18944);
        const half* Xst = (const half*)(ps + (t & 3) * 18944 + 10240);
#pragma unroll
        for (int ks = 0; ks < 32; ks += 16) {
            wmma::fragment<wmma::matrix_a, 16, 16, 16, half, wmma::row_major> a[2];
            wmma::load_matrix_sync(a[0], Wst + wo * 40 + ks, 40);
            wmma::load_matrix_sync(a[1], Wst + (wo + 16) * 40 + ks, 40);
#pragma unroll
            for (int nf = 0; nf < 4; nf++) {
                wmma::fragment<wmma::matrix_b, 16, 16, 16, half, wmma::row_major> bf;
                wmma::load_matrix_sync(bf, Xst + ks * 136 + wp + nf * 16, 136);
                wmma::mma_sync(acc[0][nf], a[0], bf, acc[0][nf]);
                wmma::mma_sync(acc[1][nf], a[1], bf, acc[1][nf]);
            }
        }
    }
    __syncthreads();

    // Epilogue: BN, convert half, store [o][p]
    float* es = &Es[warp][0];
#pragma unroll
    for (int mf = 0; mf < 2; mf++)
#pragma unroll
        for (int nf = 0; nf < 4; nf++) {
            wmma::store_matrix_sync(es, acc[mf][nf], 24, wmma::mem_row_major);
            __syncwarp();
            int r = lane >> 1, cb = (lane & 1) * 8;
            int o_l = wo + mf * 16 + r;
            float s = so[o_l], t = to[o_l];
            union { uint4 u; half h[8]; } hb;
#pragma unroll
            for (int c = 0; c < 8; c++)
                hb.h[c] = __float2half(es[r * 24 + cb + c] * s + t);
            int o = o0 + o_l;
            int p = p0 + wp + nf * 16 + cb;
            *(uint4*)(outbuf + ((size_t)(b * 512 + o) * 1024 + p)) = hb.u;
            __syncwarp();
        }
}

// ============================================================================
// Kernel 2: attention. S-GEMM in fp16 accumulate (2x legacy HMMA rate; Q
// pre-scaled by 0.125 so |S|<~5, exp-safe, fp16-acc-safe). PV in fp32 acc.
// cp.async 3-stage K/V, in-register streaming softmax, hardswish epilogue.
// smem: Qs 64x136 (17408) | Ks 3x64x72 (27648) | Vs 3x64x72 (27648) |
//       semb 4096  => 76800 B
// ============================================================================
__global__ __launch_bounds__(256, 2) void attn_kernel(const float* __restrict__ emb)
{
    extern __shared__ char smc[];
    half*  Qs   = (half*)(smc);
    half*  Ks   = (half*)(smc + 17408);
    half*  Vs   = (half*)(smc + 45056);
    float* semb = (float*)(smc + 72704);

    const int bh = blockIdx.y;
    const int b = bh >> 3, h = bh & 7;
    const int i0 = blockIdx.x * 128;
    const int tid  = threadIdx.x;
    const int warp = tid >> 5;
    const int lane = tid & 31;
    const int g    = lane >> 2;
    const int tig  = lane & 3;

    const half* Qg = g_q + (size_t)(b * 512 + h * 64) * 1024;
    const half* Kg = g_k + (size_t)(b * 512 + h * 64) * 1024;
    const half* Vg = g_v + (size_t)(b * 512 + h * 64) * 1024;

    const uint32_t qsm = smem_u32(Qs);
    const uint32_t ksm = smem_u32(Ks);
    const uint32_t vsm = smem_u32(Vs);

    for (int i = tid; i < 1024; i += 256)
        semb[i] = emb[i * 8 + h] * 8.0f;

    // Q: 64 d-rows x 128 i, stride 136 (natural [d][i], no transpose)
#pragma unroll
    for (int u = 0; u < 4; u++) {
        int c = tid + u * 256;
        int d = c >> 4, io = (c & 15) * 8;
        cp16(qsm + (d * 136 + io) * 2, Qg + (size_t)d * 1024 + i0 + io);
    }

    auto issue_kv = [&](int t, int s) {
        int j0 = t * 64;
        uint32_t kb = ksm + s * 9216, vb = vsm + s * 9216;
#pragma unroll
        for (int u = 0; u < 2; u++) {
            int c = tid + u * 256;
            int d = c >> 3, jo = (c & 7) * 8;
            cp16(kb + (d * 72 + jo) * 2, Kg + (size_t)d * 1024 + j0 + jo);
            cp16(vb + (d * 72 + jo) * 2, Vg + (size_t)d * 1024 + j0 + jo);
        }
    };

    issue_kv(0, 0); cp_commit();   // G0 (with Q)
    issue_kv(1, 1); cp_commit();   // G1
    cp_wait<1>();                  // G0 done
    __syncthreads();

    // Q A-fragments via ldmatrix.trans from [d][i]
    const int iw = warp * 16;
    const int l = lane;
    const int qRow = (l & 7) + (l >> 4) * 8;            // d-row within 16
    const int qCol = iw + ((l >> 3) & 1) * 8;           // i (+8 for a1/a3)
    uint32_t qa[4][4];
#pragma unroll
    for (int dk = 0; dk < 4; dk++)
        ldsm_x4_t(qa[dk][0], qa[dk][1], qa[dk][2], qa[dk][3],
                  qsm + ((dk * 16 + qRow) * 136 + qCol) * 2);

    const int kRow  = (l & 7) + ((l >> 3) & 1) * 8;     // d within 16 (b0/b1)
    const int kCol8 = (l >> 4) * 8;                     // j +8 for second nf
    const int vRow  = (l & 7) + (l >> 4) * 8;           // d (n-dim)
    const int vCol8 = ((l >> 3) & 1) * 8;               // j +8 for b1

    const int ig  = i0 + iw + g;
    const int ig8 = ig + 8;
    const int xi0 = ig >> 5,  yi0 = ig & 31;
    const int xi8 = ig8 >> 5, yi8 = ig8 & 31;

    float oacc[8][4];
#pragma unroll
    for (int nf = 0; nf < 8; nf++)
#pragma unroll
        for (int c = 0; c < 4; c++) oacc[nf][c] = 0.0f;
    float l0 = 0.0f, l1 = 0.0f;

    for (int t = 0; t < 16; t++) {
        if (t < 15) cp_wait<1>(); else cp_wait<0>();
        __syncthreads();
        if (t + 2 < 16) { issue_kv(t + 2, (t + 2) % 3); cp_commit(); }

        const uint32_t kb = ksm + (t % 3) * 9216;
        const uint32_t vb = vsm + (t % 3) * 9216;

        // S = (0.125 Q) K^T, fp16 accumulate (Q pre-scaled at projection)
        uint32_t sacch[8][2];
#pragma unroll
        for (int nf = 0; nf < 8; nf++) { sacch[nf][0] = 0u; sacch[nf][1] = 0u; }
#pragma unroll
        for (int dk = 0; dk < 4; dk++) {
#pragma unroll
            for (int nfp = 0; nfp < 4; nfp++) {
                uint32_t b0a, b1a, b0b, b1b;
                ldsm_x4_t(b0a, b1a, b0b, b1b,
                          kb + ((dk * 16 + kRow) * 72 + nfp * 16 + kCol8) * 2);
                mma16816_h(sacch[2 * nfp],     qa[dk], b0a, b1a);
                mma16816_h(sacch[2 * nfp + 1], qa[dk], b0b, b1b);
            }
        }

        // bias + exp, in registers; repack P directly as fp16 A-operands
        const int jt = t * 64 + 2 * tig;
        uint32_t ph[8][2];   // ph[nf][0] = rows g pair, [1] = rows g+8 pair
#pragma unroll
        for (int nf = 0; nf < 8; nf++) {
            int j0e = jt + nf * 8;
            int xj0 = j0e >> 5,       yj0 = j0e & 31;
            int xj1 = (j0e + 1) >> 5, yj1 = (j0e + 1) & 31;
            float bi00 = semb[abs(xi0 - xj0) * 32 + abs(yi0 - yj0)];
            float bi01 = semb[abs(xi0 - xj1) * 32 + abs(yi0 - yj1)];
            float bi10 = semb[abs(xi8 - xj0) * 32 + abs(yi8 - yj0)];
            float bi11 = semb[abs(xi8 - xj1) * 32 + abs(yi8 - yj1)];
            float2 lo = __half22float2(*(const __half2*)&sacch[nf][0]);
            float2 hi = __half22float2(*(const __half2*)&sacch[nf][1]);
            float e0 = __expf(lo.x + bi00);
            float e1 = __expf(lo.y + bi01);
            float e2 = __expf(hi.x + bi10);
            float e3 = __expf(hi.y + bi11);
            l0 += e0 + e1;
            l1 += e2 + e3;
            ph[nf][0] = packh2(e0, e1);
            ph[nf][1] = packh2(e2, e3);
        }

        // O += P V (fp32 accumulate; V non-trans ldmatrix from natural [d][j])
#pragma unroll
        for (int kf = 0; kf < 4; kf++) {
            uint32_t pa[4];
            pa[0] = ph[2 * kf][0];
            pa[1] = ph[2 * kf][1];
            pa[2] = ph[2 * kf + 1][0];
            pa[3] = ph[2 * kf + 1][1];
#pragma unroll
            for (int nfp = 0; nfp < 4; nfp++) {
                uint32_t v0a, v1a, v0b, v1b;
                ldsm_x4(v0a, v1a, v0b, v1b,
                        vb + ((nfp * 16 + vRow) * 72 + kf * 16 + vCol8) * 2);
                mma16816(oacc[2 * nfp],     pa, v0a, v1a);
                mma16816(oacc[2 * nfp + 1], pa, v0b, v1b);
            }
        }
    }

    // row-sum reduction within quad, normalize, hardswish, store
    l0 += __shfl_xor_sync(0xffffffffu, l0, 1);
    l0 += __shfl_xor_sync(0xffffffffu, l0, 2);
    l1 += __shfl_xor_sync(0xffffffffu, l1, 1);
    l1 += __shfl_xor_sync(0xffffffffu, l1, 2);
    float inv0 = 1.0f / l0, inv1 = 1.0f / l1;

    half* dst0 = g_o + ((size_t)(b * 1024 + ig)  * 512 + h * 64);
    half* dst1 = g_o + ((size_t)(b * 1024 + ig8) * 512 + h * 64);
#pragma unroll
    for (int nf = 0; nf < 8; nf++) {
        *(__half2*)(dst0 + nf * 8 + 2 * tig) =
            __floats2half2_rn(hswish_f(oacc[nf][0] * inv0), hswish_f(oacc[nf][1] * inv0));
        *(__half2*)(dst1 + nf * 8 + 2 * tig) =
            __floats2half2_rn(hswish_f(oacc[nf][2] * inv1), hswish_f(oacc[nf][3] * inv1));
    }
}

// ============================================================================
// Kernel 3: output GEMM (pure fp16, cp.async 4-stage) + bias + BN.
// smem: 4 stages x (As 10240 + Bs 10240) = 81920 B.
// ============================================================================
__global__ __launch_bounds__(256, 2) void outproj_kernel(
    const float* __restrict__ b_out,
    const float* __restrict__ gam, const float* __restrict__ bet,
    const float* __restrict__ mu, const float* __restrict__ var,
    float* __restrict__ out)
{
    extern __shared__ char ps[];
    __shared__ float so[128], to[128], bo_s[128];
    __shared__ float Es[8][384];

    const int b  = blockIdx.z;
    const int o0 = blockIdx.y * 128;
    const int p0 = blockIdx.x * 128;
    const int tid  = threadIdx.x;
    const int warp = tid >> 5;
    const int lane = tid & 31;
    const half* Ob = g_o + (size_t)b * 1024 * 512;

    if (tid < 128) {
        int o = o0 + tid;
        float s = gam[o] * rsqrtf(var[o] + EPS);
        so[tid] = s;
        to[tid] = bet[o] - mu[o] * s;
        bo_s[tid] = b_out[o];
    }

    const uint32_t sm0 = smem_u32(ps);
    auto issue = [&](int t, int s) {
        int kk = t * 32;
        uint32_t base = sm0 + s * 20480;
#pragma unroll
        for (int u = 0; u < 2; u++) {
            int c = tid + u * 256;
            int r = c >> 2, ko = (c & 3) * 8;
            cp16(base + (r * 40 + ko) * 2, Ob + (size_t)(p0 + r) * 512 + kk + ko);
            cp16(base + 10240 + (r * 40 + ko) * 2, g_w216 + (size_t)(o0 + r) * 512 + kk + ko);
        }
    };

    const int wp = (warp >> 1) * 32;
    const int wo = (warp & 1) * 64;

    wmma::fragment<wmma::accumulator, 16, 16, 16, float> acc[2][4];
#pragma unroll
    for (int i = 0; i < 2; i++)
#pragma unroll
        for (int j = 0; j < 4; j++) wmma::fill_fragment(acc[i][j], 0.0f);

    issue(0, 0); cp_commit();
    issue(1, 1); cp_commit();
    issue(2, 2); cp_commit();

    for (int t = 0; t < 16; t++) {
        if (t + 2 < 16)      cp_wait<2>();
        else if (t + 1 < 16) cp_wait<1>();
        else                 cp_wait<0>();
        __syncthreads();
        if (t + 3 < 16) { issue(t + 3, (t + 3) & 3); cp_commit(); }
        const half* As = (const half*)(ps + (t & 3) * 20480);
        const half* Bs = (const half*)(ps + (t & 3) * 20480 + 10240);
#pragma unroll
        for (int ks = 0; ks < 32; ks += 16) {
            wmma::fragment<wmma::matrix_a, 16, 16, 16, half, wmma::row_major> a[2];
            wmma::load_matrix_sync(a[0], As + wp * 40 + ks, 40);
            wmma::load_matrix_sync(a[1], As + (wp + 16) * 40 + ks, 40);
#pragma unroll
            for (int nf = 0; nf < 4; nf++) {
                wmma::fragment<wmma::matrix_b, 16, 16, 16, half, wmma::col_major> bf;
                wmma::load_matrix_sync(bf, Bs + (wo + nf * 16) * 40 + ks, 40);
                wmma::mma_sync(acc[0][nf], a[0], bf, acc[0][nf]);
                wmma::mma_sync(acc[1][nf], a[1], bf, acc[1][nf]);
            }
        }
    }
    __syncthreads();

    // Epilogue: acc (m=p, n=o); col-major store -> es[o][p], BN per o, fp32 out
    float* es = &Es[warp][0];
#pragma unroll
    for (int mf = 0; mf < 2; mf++)
#pragma unroll
        for (int nf = 0; nf < 4; nf++) {
            wmma::store_matrix_sync(es, acc[mf][nf], 24, wmma::mem_col_major);
            __syncwarp();
            int r = lane >> 1, cb = (lane & 1) * 8;
            int o_l = wo + nf * 16 + r;
            int p_l = wp + mf * 16 + cb;
            float s = so[o_l], t = to[o_l], bb = bo_s[o_l];
            float* dst = out + (size_t)(b * 256 + o0 + o_l) * 1024 + p0 + p_l;
            const float* er = es + r * 24 + cb;
            float4 v0, v1;
            v0.x = (er[0] + bb) * s + t;  v0.y = (er[1] + bb) * s + t;
            v0.z = (er[2] + bb) * s + t;  v0.w = (er[3] + bb) * s + t;
            v1.x = (er[4] + bb) * s + t;  v1.y = (er[5] + bb) * s + t;
            v1.z = (er[6] + bb) * s + t;  v1.w = (er[7] + bb) * s + t;
            *(float4*)dst = v0;
            *(float4*)(dst + 4) = v1;
            __syncwarp();
        }
}

// ============================================================================
extern "C" void kernel_launch(void* const* d_in, const int* in_sizes, int n_in,
                              void* d_out, int out_size)
{
    const float* x    = (const float*)d_in[0];
    const float* wq   = (const float*)d_in[1];
    const float* gq   = (const float*)d_in[2];
    const float* bq   = (const float*)d_in[3];
    const float* mq   = (const float*)d_in[4];
    const float* vq   = (const float*)d_in[5];
    const float* wk   = (const float*)d_in[6];
    const float* gk   = (const float*)d_in[7];
    const float* bk   = (const float*)d_in[8];
    const float* mk   = (const float*)d_in[9];
    const float* vk   = (const float*)d_in[10];
    const float* wv   = (const float*)d_in[11];
    const float* gv   = (const float*)d_in[12];
    const float* bv   = (const float*)d_in[13];
    const float* mv   = (const float*)d_in[14];
    const float* vv   = (const float*)d_in[15];
    const float* emb  = (const float*)d_in[16];
    const float* w_o  = (const float*)d_in[17];
    const float* b_o  = (const float*)d_in[18];
    const float* go   = (const float*)d_in[19];
    const float* bo   = (const float*)d_in[20];
    const float* mo   = (const float*)d_in[21];
    const float* vo   = (const float*)d_in[22];
    // d_in[23] = pos_indices: recomputed on the fly in attn_kernel, unused.

    cudaFuncSetAttribute(proj_kernel,    cudaFuncAttributeMaxDynamicSharedMemorySize, 75776);
    cudaFuncSetAttribute(attn_kernel,    cudaFuncAttributeMaxDynamicSharedMemorySize, 76800);
    cudaFuncSetAttribute(outproj_kernel, cudaFuncAttributeMaxDynamicSharedMemorySize, 81920);
    cudaFuncSetAttribute(proj_kernel,    cudaFuncAttributePreferredSharedMemoryCarveout, 100);
    cudaFuncSetAttribute(attn_kernel,    cudaFuncAttributePreferredSharedMemoryCarveout, 100);
    cudaFuncSetAttribute(outproj_kernel, cudaFuncAttributePreferredSharedMemoryCarveout, 100);

    convert_kernel<<<4608, 256>>>(x, wq, wk, wv, w_o);
    proj_kernel<<<dim3(8, 4, 48), 256, 75776>>>(gq, bq, mq, vq,
                                                gk, bk, mk, vk,
                                                gv, bv, mv, vv);
    attn_kernel<<<dim3(8, 128), 256, 76800>>>(emb);
    outproj_kernel<<<dim3(8, 2, 16), 256, 81920>>>(b_o, go, bo, mo, vo, (float*)d_out);
}

// round 17
// speedup vs baseline: 1.2061x; 1.2025x over previous
#include <cuda_runtime.h>
#include <cuda_fp16.h>
#include <mma.h>
#include <cstdint>

using namespace nvcuda;

#define EPS 1e-5f

// ---- scratch (static device globals; no allocation at runtime) ----
static __device__ half g_x16[16 * 256 * 1024];  // X converted to half [b][c][p]
static __device__ half g_wq16[512 * 256];
static __device__ half g_wk16[512 * 256];
static __device__ half g_wv16[512 * 256];
static __device__ half g_w216[256 * 512];
static __device__ half g_q[16 * 512 * 1024];    // [b, h*64+d, i], pre-scaled by 0.125*log2e
static __device__ half g_k[16 * 512 * 1024];    // [b, h*64+d, j]
static __device__ half g_v[16 * 512 * 1024];    // [b, h*64+d, j]
static __device__ half g_o[16 * 1024 * 512];    // [b, i, h*64+d], hardswish applied

__device__ __forceinline__ float hswish_f(float x) {
    return x * __saturatef((x + 3.0f) * (1.0f / 6.0f));
}

__device__ __forceinline__ uint32_t smem_u32(const void* p) {
    return (uint32_t)__cvta_generic_to_shared(p);
}
__device__ __forceinline__ void cp16(uint32_t dst, const void* src) {
    asm volatile("cp.async.cg.shared.global [%0], [%1], 16;" :: "r"(dst), "l"(src));
}
__device__ __forceinline__ void cp_commit() { asm volatile("cp.async.commit_group;"); }
template<int N> __device__ __forceinline__ void cp_wait() {
    asm volatile("cp.async.wait_group %0;" :: "n"(N));
}
__device__ __forceinline__ void ldsm_x4(uint32_t& r0, uint32_t& r1, uint32_t& r2, uint32_t& r3, uint32_t a) {
    asm volatile("ldmatrix.sync.aligned.m8n8.x4.shared.b16 {%0,%1,%2,%3}, [%4];"
        : "=r"(r0), "=r"(r1), "=r"(r2), "=r"(r3) : "r"(a));
}
__device__ __forceinline__ void ldsm_x4_t(uint32_t& r0, uint32_t& r1, uint32_t& r2, uint32_t& r3, uint32_t a) {
    asm volatile("ldmatrix.sync.aligned.m8n8.x4.trans.shared.b16 {%0,%1,%2,%3}, [%4];"
        : "=r"(r0), "=r"(r1), "=r"(r2), "=r"(r3) : "r"(a));
}

// mma.sync m16n8k16 row.col f32 accumulate, in place
__device__ __forceinline__ void mma16816(float* d, const uint32_t* a, uint32_t b0, uint32_t b1) {
    asm volatile(
        "mma.sync.aligned.m16n8k16.row.col.f32.f16.f16.f32 "
        "{%0,%1,%2,%3}, {%4,%5,%6,%7}, {%8,%9}, {%0,%1,%2,%3};\n"
        : "+f"(d[0]), "+f"(d[1]), "+f"(d[2]), "+f"(d[3])
        : "r"(a[0]), "r"(a[1]), "r"(a[2]), "r"(a[3]), "r"(b0), "r"(b1));
}

// mma.sync m16n8k16 row.col fp16 accumulate (2 packed half2 regs), in place
__device__ __forceinline__ void mma16816_h(uint32_t* d, const uint32_t* a, uint32_t b0, uint32_t b1) {
    asm volatile(
        "mma.sync.aligned.m16n8k16.row.col.f16.f16.f16.f16 "
        "{%0,%1}, {%2,%3,%4,%5}, {%6,%7}, {%0,%1};\n"
        : "+r"(d[0]), "+r"(d[1])
        : "r"(a[0]), "r"(a[1]), "r"(a[2]), "r"(a[3]), "r"(b0), "r"(b1));
}

__device__ __forceinline__ uint32_t ex2_h2(uint32_t x) {
    uint32_t r;
    asm("ex2.approx.f16x2 %0, %1;" : "=r"(r) : "r"(x));
    return r;
}

// ============================================================================
// Kernel 0: convert fp32 inputs to fp16 globals (4 floats per thread).
// ============================================================================
__global__ __launch_bounds__(256) void convert_kernel(
    const float* __restrict__ X, const float* __restrict__ Wq,
    const float* __restrict__ Wk, const float* __restrict__ Wv,
    const float* __restrict__ W2)
{
    int i = blockIdx.x * 256 + threadIdx.x;   // float4 index
    const int NX = 1048576, NW = 32768;       // in float4 units
    const float* src; half* dst; int off;
    if (i < NX)                 { src = X;  dst = g_x16;  off = i; }
    else if (i < NX + NW)       { src = Wq; dst = g_wq16; off = i - NX; }
    else if (i < NX + 2 * NW)   { src = Wk; dst = g_wk16; off = i - NX - NW; }
    else if (i < NX + 3 * NW)   { src = Wv; dst = g_wv16; off = i - NX - 2 * NW; }
    else if (i < NX + 4 * NW)   { src = W2; dst = g_w216; off = i - NX - 3 * NW; }
    else return;
    float4 f = ((const float4*)src)[off];
    half2* d2 = (half2*)(dst + (size_t)off * 4);
    d2[0] = __floats2half2_rn(f.x, f.y);
    d2[1] = __floats2half2_rn(f.z, f.w);
}

// ============================================================================
// Kernel 1: fused Q/K/V projection GEMM (fp16 wmma, cp.async 4-stage) + BN.
// Q is additionally pre-scaled by 0.125*log2e (attention scale + exp2 fold).
// smem: 4 stages x (Ws 128x40 = 10240B | Xs 32x136 = 8704B) = 75776 B.
// ============================================================================
__global__ __launch_bounds__(256, 2) void proj_kernel(
    const float* __restrict__ gq, const float* __restrict__ bq,
    const float* __restrict__ mq, const float* __restrict__ vq,
    const float* __restrict__ gk, const float* __restrict__ bk,
    const float* __restrict__ mk, const float* __restrict__ vk,
    const float* __restrict__ gv, const float* __restrict__ bv,
    const float* __restrict__ mv, const float* __restrict__ vv)
{
    extern __shared__ char ps[];
    __shared__ float so[128], to[128];
    __shared__ float Es[8][384];

    const int which = blockIdx.z >> 4;
    const int b     = blockIdx.z & 15;
    const half* W    = (which == 0) ? g_wq16 : (which == 1) ? g_wk16 : g_wv16;
    const float* gam = (which == 0) ? gq : (which == 1) ? gk : gv;
    const float* bet = (which == 0) ? bq : (which == 1) ? bk : bv;
    const float* mu  = (which == 0) ? mq : (which == 1) ? mk : mv;
    const float* var = (which == 0) ? vq : (which == 1) ? vk : vv;
    half* outbuf     = (which == 0) ? g_q : (which == 1) ? g_k : g_v;
    const float qs   = (which == 0) ? 0.18033688f : 1.0f;   // 0.125 * log2(e)

    const int o0 = blockIdx.y * 128;
    const int p0 = blockIdx.x * 128;
    const int tid  = threadIdx.x;
    const int warp = tid >> 5;
    const int lane = tid & 31;
    const half* Xb = g_x16 + (size_t)b * 256 * 1024;

    if (tid < 128) {
        int o = o0 + tid;
        float s = gam[o] * rsqrtf(var[o] + EPS);
        so[tid] = s * qs;
        to[tid] = (bet[o] - mu[o] * s) * qs;
    }

    const uint32_t sm0 = smem_u32(ps);
    auto issue = [&](int t, int s) {
        int kk = t * 32;
        uint32_t base = sm0 + s * 18944;
#pragma unroll
        for (int u = 0; u < 2; u++) {
            int c = tid + u * 256;                  // 0..511
            int o = c >> 2, ko = (c & 3) * 8;
            cp16(base + (o * 40 + ko) * 2, W + (size_t)(o0 + o) * 256 + kk + ko);
            int kc = c >> 4, po = (c & 15) * 8;
            cp16(base + 10240 + (kc * 136 + po) * 2, Xb + (size_t)(kk + kc) * 1024 + p0 + po);
        }
    };

    const int wo = (warp >> 1) * 32;
    const int wp = (warp & 1) * 64;

    wmma::fragment<wmma::accumulator, 16, 16, 16, float> acc[2][4];
#pragma unroll
    for (int i = 0; i < 2; i++)
#pragma unroll
        for (int j = 0; j < 4; j++) wmma::fill_fragment(acc[i][j], 0.0f);

    issue(0, 0); cp_commit();
    issue(1, 1); cp_commit();
    issue(2, 2); cp_commit();

    for (int t = 0; t < 8; t++) {
        if (t + 2 < 8)      cp_wait<2>();
        else if (t + 1 < 8) cp_wait<1>();
        else                cp_wait<0>();
        __syncthreads();
        if (t + 3 < 8) { issue(t + 3, (t + 3) & 3); cp_commit(); }
        const half* Wst = (const half*)(ps + (t & 3) * 18944);
        const half* Xst = (const half*)(ps + (t & 3) * 18944 + 10240);
#pragma unroll
        for (int ks = 0; ks < 32; ks += 16) {
            wmma::fragment<wmma::matrix_a, 16, 16, 16, half, wmma::row_major> a[2];
            wmma::load_matrix_sync(a[0], Wst + wo * 40 + ks, 40);
            wmma::load_matrix_sync(a[1], Wst + (wo + 16) * 40 + ks, 40);
#pragma unroll
            for (int nf = 0; nf < 4; nf++) {
                wmma::fragment<wmma::matrix_b, 16, 16, 16, half, wmma::row_major> bf;
                wmma::load_matrix_sync(bf, Xst + ks * 136 + wp + nf * 16, 136);
                wmma::mma_sync(acc[0][nf], a[0], bf, acc[0][nf]);
                wmma::mma_sync(acc[1][nf], a[1], bf, acc[1][nf]);
            }
        }
    }
    __syncthreads();

    // Epilogue: BN, convert half, store [o][p]
    float* es = &Es[warp][0];
#pragma unroll
    for (int mf = 0; mf < 2; mf++)
#pragma unroll
        for (int nf = 0; nf < 4; nf++) {
            wmma::store_matrix_sync(es, acc[mf][nf], 24, wmma::mem_row_major);
            __syncwarp();
            int r = lane >> 1, cb = (lane & 1) * 8;
            int o_l = wo + mf * 16 + r;
            float s = so[o_l], t = to[o_l];
            union { uint4 u; half h[8]; } hb;
#pragma unroll
            for (int c = 0; c < 8; c++)
                hb.h[c] = __float2half(es[r * 24 + cb + c] * s + t);
            int o = o0 + o_l;
            int p = p0 + wp + nf * 16 + cb;
            *(uint4*)(outbuf + ((size_t)(b * 512 + o) * 1024 + p)) = hb.u;
            __syncwarp();
        }
}

// ============================================================================
// Kernel 2: attention. S-GEMM fp16 acc (Q pre-scaled by 0.125*log2e), softmax
// via ex2.approx.f16x2 on packed pairs (no unpack/pack), bias from precomputed
// half2 pair-LUTs (ascending/descending) with loop-invariant base offsets.
// PV fp32 acc. cp.async 3-stage K/V. hardswish fused epilogue.
// smem: Qs 17408 | Ks 27648 | Vs 27648 | sembA 4096 | sembD 4096 = 80896 B
// ============================================================================
__global__ __launch_bounds__(256, 2) void attn_kernel(const float* __restrict__ emb)
{
    extern __shared__ char smc[];
    half*  Qs   = (half*)(smc);
    half*  Ks   = (half*)(smc + 17408);
    half*  Vs   = (half*)(smc + 45056);
    __half2* sembA = (__half2*)(smc + 72704);   // [k] = (v[k], v[k+1])
    __half2* sembD = (__half2*)(smc + 76800);   // [k] = (v[k], v[k-1])

    const int bh = blockIdx.y;
    const int b = bh >> 3, h = bh & 7;
    const int i0 = blockIdx.x * 128;
    const int tid  = threadIdx.x;
    const int warp = tid >> 5;
    const int lane = tid & 31;
    const int g    = lane >> 2;
    const int tig  = lane & 3;

    const half* Qg = g_q + (size_t)(b * 512 + h * 64) * 1024;
    const half* Kg = g_k + (size_t)(b * 512 + h * 64) * 1024;
    const half* Vg = g_v + (size_t)(b * 512 + h * 64) * 1024;

    const uint32_t qsm = smem_u32(Qs);
    const uint32_t ksm = smem_u32(Ks);
    const uint32_t vsm = smem_u32(Vs);
    const uint32_t sAa = smem_u32(sembA);
    const uint32_t sDa = smem_u32(sembD);

    // Build bias pair-LUTs: v[k] = emb[k*8+h] * 8 * log2(e)
    {
        const float C = 8.0f * 1.44269504f;
        for (int k = tid; k < 1024; k += 256) {
            float vk = emb[k * 8 + h] * C;
            float vp = (k < 1023) ? emb[(k + 1) * 8 + h] * C : vk;
            float vm = (k > 0)    ? emb[(k - 1) * 8 + h] * C : vk;
            sembA[k] = __floats2half2_rn(vk, vp);
            sembD[k] = __floats2half2_rn(vk, vm);
        }
    }

    // Q: 64 d-rows x 128 i, stride 136 (natural [d][i], no transpose)
#pragma unroll
    for (int u = 0; u < 4; u++) {
        int c = tid + u * 256;
        int d = c >> 4, io = (c & 15) * 8;
        cp16(qsm + (d * 136 + io) * 2, Qg + (size_t)d * 1024 + i0 + io);
    }

    auto issue_kv = [&](int t, int s) {
        int j0 = t * 64;
        uint32_t kb = ksm + s * 9216, vb = vsm + s * 9216;
#pragma unroll
        for (int u = 0; u < 2; u++) {
            int c = tid + u * 256;
            int d = c >> 3, jo = (c & 7) * 8;
            cp16(kb + (d * 72 + jo) * 2, Kg + (size_t)d * 1024 + j0 + jo);
            cp16(vb + (d * 72 + jo) * 2, Vg + (size_t)d * 1024 + j0 + jo);
        }
    };

    issue_kv(0, 0); cp_commit();   // G0 (with Q)
    issue_kv(1, 1); cp_commit();   // G1
    cp_wait<1>();                  // G0 done
    __syncthreads();

    // Q A-fragments via ldmatrix.trans from [d][i]
    const int iw = warp * 16;
    const int l = lane;
    const int qRow = (l & 7) + (l >> 4) * 8;            // d-row within 16
    const int qCol = iw + ((l >> 3) & 1) * 8;           // i (+8 for a1/a3)
    uint32_t qa[4][4];
#pragma unroll
    for (int dk = 0; dk < 4; dk++)
        ldsm_x4_t(qa[dk][0], qa[dk][1], qa[dk][2], qa[dk][3],
                  qsm + ((dk * 16 + qRow) * 136 + qCol) * 2);

    const int kRow  = (l & 7) + ((l >> 3) & 1) * 8;     // d within 16 (b0/b1)
    const int kCol8 = (l >> 4) * 8;                     // j +8 for second nf
    const int vRow  = (l & 7) + (l >> 4) * 8;           // d (n-dim)
    const int vCol8 = ((l >> 3) & 1) * 8;               // j +8 for b1

    const int ig  = i0 + iw + g;
    const int ig8 = ig + 8;
    const int xi0 = ig >> 5,  yi0 = ig & 31;
    const int xi8 = ig8 >> 5, yi8 = ig8 & 31;

    // Loop-invariant bias base addresses per (nf, row):
    // yj = (nf*8 + 2*tig) & 31 is constant; c_nf = (nf>=4).
    uint32_t boff[8][2];
#pragma unroll
    for (int nf = 0; nf < 8; nf++) {
        int q = nf * 8 + 2 * tig;
        int yj = q & 31;
        boff[nf][0] = (yi0 <= yj) ? (sAa + (uint32_t)(yj - yi0) * 4)
                                  : (sDa + (uint32_t)(yi0 - yj) * 4);
        boff[nf][1] = (yi8 <= yj) ? (sAa + (uint32_t)(yj - yi8) * 4)
                                  : (sDa + (uint32_t)(yi8 - yj) * 4);
    }

    float oacc[8][4];
#pragma unroll
    for (int nf = 0; nf < 8; nf++)
#pragma unroll
        for (int c = 0; c < 4; c++) oacc[nf][c] = 0.0f;
    float l0 = 0.0f, l1 = 0.0f;

    for (int t = 0; t < 16; t++) {
        if (t < 15) cp_wait<1>(); else cp_wait<0>();
        __syncthreads();
        if (t + 2 < 16) { issue_kv(t + 2, (t + 2) % 3); cp_commit(); }

        const uint32_t kb = ksm + (t % 3) * 9216;
        const uint32_t vb = vsm + (t % 3) * 9216;

        // S' = (0.125*log2e * Q) K^T, fp16 accumulate
        uint32_t sacch[8][2];
#pragma unroll
        for (int nf = 0; nf < 8; nf++) { sacch[nf][0] = 0u; sacch[nf][1] = 0u; }
#pragma unroll
        for (int dk = 0; dk < 4; dk++) {
#pragma unroll
            for (int nfp = 0; nfp < 4; nfp++) {
                uint32_t b0a, b1a, b0b, b1b;
                ldsm_x4_t(b0a, b1a, b0b, b1b,
                          kb + ((dk * 16 + kRow) * 72 + nfp * 16 + kCol8) * 2);
                mma16816_h(sacch[2 * nfp],     qa[dk], b0a, b1a);
                mma16816_h(sacch[2 * nfp + 1], qa[dk], b0b, b1b);
            }
        }

        // softmax: P = exp2(S' + bias'), all in packed half2
        {
            int tt = 2 * t;
            uint32_t dxo00 = (uint32_t)abs(xi0 - tt) << 7;
            uint32_t dxo01 = (uint32_t)abs(xi0 - tt - 1) << 7;
            uint32_t dxo10 = (uint32_t)abs(xi8 - tt) << 7;
            uint32_t dxo11 = (uint32_t)abs(xi8 - tt - 1) << 7;
#pragma unroll
            for (int nf = 0; nf < 8; nf++) {
                uint32_t d0 = (nf >= 4) ? dxo01 : dxo00;
                uint32_t d1 = (nf >= 4) ? dxo11 : dxo10;
                uint32_t bi0, bi1;
                asm volatile("ld.shared.b32 %0, [%1];" : "=r"(bi0) : "r"(boff[nf][0] + d0));
                asm volatile("ld.shared.b32 %0, [%1];" : "=r"(bi1) : "r"(boff[nf][1] + d1));
                __half2 s0 = __hadd2(*(__half2*)&sacch[nf][0], *(__half2*)&bi0);
                __half2 s1 = __hadd2(*(__half2*)&sacch[nf][1], *(__half2*)&bi1);
                sacch[nf][0] = ex2_h2(*(uint32_t*)&s0);
                sacch[nf][1] = ex2_h2(*(uint32_t*)&s1);
            }
            // l tree-sums (fp16 within tile, fp32 across tiles)
            __half2 a0 = __hadd2(*(__half2*)&sacch[0][0], *(__half2*)&sacch[1][0]);
            __half2 a1 = __hadd2(*(__half2*)&sacch[2][0], *(__half2*)&sacch[3][0]);
            __half2 a2 = __hadd2(*(__half2*)&sacch[4][0], *(__half2*)&sacch[5][0]);
            __half2 a3 = __hadd2(*(__half2*)&sacch[6][0], *(__half2*)&sacch[7][0]);
            __half2 u0 = __hadd2(__hadd2(a0, a1), __hadd2(a2, a3));
            float2 f0 = __half22float2(u0);
            l0 += f0.x + f0.y;
            __half2 b0h = __hadd2(*(__half2*)&sacch[0][1], *(__half2*)&sacch[1][1]);
            __half2 b1h = __hadd2(*(__half2*)&sacch[2][1], *(__half2*)&sacch[3][1]);
            __half2 b2h = __hadd2(*(__half2*)&sacch[4][1], *(__half2*)&sacch[5][1]);
            __half2 b3h = __hadd2(*(__half2*)&sacch[6][1], *(__half2*)&sacch[7][1]);
            __half2 u1 = __hadd2(__hadd2(b0h, b1h), __hadd2(b2h, b3h));
            float2 f1 = __half22float2(u1);
            l1 += f1.x + f1.y;
        }

        // O += P V (fp32 accumulate; P fragments already packed as A-operands)
#pragma unroll
        for (int kf = 0; kf < 4; kf++) {
            uint32_t pa[4];
            pa[0] = sacch[2 * kf][0];
            pa[1] = sacch[2 * kf][1];
            pa[2] = sacch[2 * kf + 1][0];
            pa[3] = sacch[2 * kf + 1][1];
#pragma unroll
            for (int nfp = 0; nfp < 4; nfp++) {
                uint32_t v0a, v1a, v0b, v1b;
                ldsm_x4(v0a, v1a, v0b, v1b,
                        vb + ((nfp * 16 + vRow) * 72 + kf * 16 + vCol8) * 2);
                mma16816(oacc[2 * nfp],     pa, v0a, v1a);
                mma16816(oacc[2 * nfp + 1], pa, v0b, v1b);
            }
        }
    }

    // row-sum reduction within quad, normalize, hardswish, store
    l0 += __shfl_xor_sync(0xffffffffu, l0, 1);
    l0 += __shfl_xor_sync(0xffffffffu, l0, 2);
    l1 += __shfl_xor_sync(0xffffffffu, l1, 1);
    l1 += __shfl_xor_sync(0xffffffffu, l1, 2);
    float inv0 = 1.0f / l0, inv1 = 1.0f / l1;

    half* dst0 = g_o + ((size_t)(b * 1024 + ig)  * 512 + h * 64);
    half* dst1 = g_o + ((size_t)(b * 1024 + ig8) * 512 + h * 64);
#pragma unroll
    for (int nf = 0; nf < 8; nf++) {
        *(__half2*)(dst0 + nf * 8 + 2 * tig) =
            __floats2half2_rn(hswish_f(oacc[nf][0] * inv0), hswish_f(oacc[nf][1] * inv0));
        *(__half2*)(dst1 + nf * 8 + 2 * tig) =
            __floats2half2_rn(hswish_f(oacc[nf][2] * inv1), hswish_f(oacc[nf][3] * inv1));
    }
}

// ============================================================================
// Kernel 3: output GEMM (pure fp16, cp.async 4-stage) + bias + BN.
// smem: 4 stages x (As 10240 + Bs 10240) = 81920 B.
// ============================================================================
__global__ __launch_bounds__(256, 2) void outproj_kernel(
    const float* __restrict__ b_out,
    const float* __restrict__ gam, const float* __restrict__ bet,
    const float* __restrict__ mu, const float* __restrict__ var,
    float* __restrict__ out)
{
    extern __shared__ char ps[];
    __shared__ float so[128], to[128], bo_s[128];
    __shared__ float Es[8][384];

    const int b  = blockIdx.z;
    const int o0 = blockIdx.y * 128;
    const int p0 = blockIdx.x * 128;
    const int tid  = threadIdx.x;
    const int warp = tid >> 5;
    const int lane = tid & 31;
    const half* Ob = g_o + (size_t)b * 1024 * 512;

    if (tid < 128) {
        int o = o0 + tid;
        float s = gam[o] * rsqrtf(var[o] + EPS);
        so[tid] = s;
        to[tid] = bet[o] - mu[o] * s;
        bo_s[tid] = b_out[o];
    }

    const uint32_t sm0 = smem_u32(ps);
    auto issue = [&](int t, int s) {
        int kk = t * 32;
        uint32_t base = sm0 + s * 20480;
#pragma unroll
        for (int u = 0; u < 2; u++) {
            int c = tid + u * 256;
            int r = c >> 2, ko = (c & 3) * 8;
            cp16(base + (r * 40 + ko) * 2, Ob + (size_t)(p0 + r) * 512 + kk + ko);
            cp16(base + 10240 + (r * 40 + ko) * 2, g_w216 + (size_t)(o0 + r) * 512 + kk + ko);
        }
    };

    const int wp = (warp >> 1) * 32;
    const int wo = (warp & 1) * 64;

    wmma::fragment<wmma::accumulator, 16, 16, 16, float> acc[2][4];
#pragma unroll
    for (int i = 0; i < 2; i++)
#pragma unroll
        for (int j = 0; j < 4; j++) wmma::fill_fragment(acc[i][j], 0.0f);

    issue(0, 0); cp_commit();
    issue(1, 1); cp_commit();
    issue(2, 2); cp_commit();

    for (int t = 0; t < 16; t++) {
        if (t + 2 < 16)      cp_wait<2>();
        else if (t + 1 < 16) cp_wait<1>();
        else                 cp_wait<0>();
        __syncthreads();
        if (t + 3 < 16) { issue(t + 3, (t + 3) & 3); cp_commit(); }
        const half* As = (const half*)(ps + (t & 3) * 20480);
        const half* Bs = (const half*)(ps + (t & 3) * 20480 + 10240);
#pragma unroll
        for (int ks = 0; ks < 32; ks += 16) {
            wmma::fragment<wmma::matrix_a, 16, 16, 16, half, wmma::row_major> a[2];
            wmma::load_matrix_sync(a[0], As + wp * 40 + ks, 40);
            wmma::load_matrix_sync(a[1], As + (wp + 16) * 40 + ks, 40);
#pragma unroll
            for (int nf = 0; nf < 4; nf++) {
                wmma::fragment<wmma::matrix_b, 16, 16, 16, half, wmma::col_major> bf;
                wmma::load_matrix_sync(bf, Bs + (wo + nf * 16) * 40 + ks, 40);
                wmma::mma_sync(acc[0][nf], a[0], bf, acc[0][nf]);
                wmma::mma_sync(acc[1][nf], a[1], bf, acc[1][nf]);
            }
        }
    }
    __syncthreads();

    // Epilogue: acc (m=p, n=o); col-major store -> es[o][p], BN per o, fp32 out
    float* es = &Es[warp][0];
#pragma unroll
    for (int mf = 0; mf < 2; mf++)
#pragma unroll
        for (int nf = 0; nf < 4; nf++) {
            wmma::store_matrix_sync(es, acc[mf][nf], 24, wmma::mem_col_major);
            __syncwarp();
            int r = lane >> 1, cb = (lane & 1) * 8;
            int o_l = wo + nf * 16 + r;
            int p_l = wp + mf * 16 + cb;
            float s = so[o_l], t = to[o_l], bb = bo_s[o_l];
            float* dst = out + (size_t)(b * 256 + o0 + o_l) * 1024 + p0 + p_l;
            const float* er = es + r * 24 + cb;
            float4 v0, v1;
            v0.x = (er[0] + bb) * s + t;  v0.y = (er[1] + bb) * s + t;
            v0.z = (er[2] + bb) * s + t;  v0.w = (er[3] + bb) * s + t;
            v1.x = (er[4] + bb) * s + t;  v1.y = (er[5] + bb) * s + t;
            v1.z = (er[6] + bb) * s + t;  v1.w = (er[7] + bb) * s + t;
            *(float4*)dst = v0;
            *(float4*)(dst + 4) = v1;
            __syncwarp();
        }
}

// ============================================================================
extern "C" void kernel_launch(void* const* d_in, const int* in_sizes, int n_in,
                              void* d_out, int out_size)
{
    const float* x    = (const float*)d_in[0];
    const float* wq   = (const float*)d_in[1];
    const float* gq   = (const float*)d_in[2];
    const float* bq   = (const float*)d_in[3];
    const float* mq   = (const float*)d_in[4];
    const float* vq   = (const float*)d_in[5];
    const float* wk   = (const float*)d_in[6];
    const float* gk   = (const float*)d_in[7];
    const float* bk   = (const float*)d_in[8];
    const float* mk   = (const float*)d_in[9];
    const float* vk   = (const float*)d_in[10];
    const float* wv   = (const float*)d_in[11];
    const float* gv   = (const float*)d_in[12];
    const float* bv   = (const float*)d_in[13];
    const float* mv   = (const float*)d_in[14];
    const float* vv   = (const float*)d_in[15];
    const float* emb  = (const float*)d_in[16];
    const float* w_o  = (const float*)d_in[17];
    const float* b_o  = (const float*)d_in[18];
    const float* go   = (const float*)d_in[19];
    const float* bo   = (const float*)d_in[20];
    const float* mo   = (const float*)d_in[21];
    const float* vo   = (const float*)d_in[22];
    // d_in[23] = pos_indices: recomputed on the fly in attn_kernel, unused.

    cudaFuncSetAttribute(proj_kernel,    cudaFuncAttributeMaxDynamicSharedMemorySize, 75776);
    cudaFuncSetAttribute(attn_kernel,    cudaFuncAttributeMaxDynamicSharedMemorySize, 80896);
    cudaFuncSetAttribute(outproj_kernel, cudaFuncAttributeMaxDynamicSharedMemorySize, 81920);
    cudaFuncSetAttribute(proj_kernel,    cudaFuncAttributePreferredSharedMemoryCarveout, 100);
    cudaFuncSetAttribute(attn_kernel,    cudaFuncAttributePreferredSharedMemoryCarveout, 100);
    cudaFuncSetAttribute(outproj_kernel, cudaFuncAttributePreferredSharedMemoryCarveout, 100);

    convert_kernel<<<4608, 256>>>(x, wq, wk, wv, w_o);
    proj_kernel<<<dim3(8, 4, 48), 256, 75776>>>(gq, bq, mq, vq,
                                                gk, bk, mk, vk,
                                                gv, bv, mv, vv);
    attn_kernel<<<dim3(8, 128), 256, 80896>>>(emb);
    outproj_kernel<<<dim3(8, 2, 16), 256, 81920>>>(b_o, go, bo, mo, vo, (float*)d_out);
}